// round 11
// baseline (speedup 1.0000x reference)
#include <cuda_runtime.h>
#include <cuda_bf16.h>
#include <math.h>
#include <stdint.h>

#define S 2048
#define R 384
#define DN 64
#define STILE 64
#define NST (S/STILE)   // 32 tiles for kA
#define SKC 128         // s-rows per kC block
#define NKC (S/SKC)     // 16
#define WPAD 2304       // uint32 words per padded 64x144B weight tile

// ---------------- scratch (static device memory; no allocations) ----------------
__device__ __align__(16) float  d_kv[R*S*16];        // per (r,s): k[8], v[8]
__device__ __align__(16) float2 d_stats[R*S];        // per (r,s): (mu, rstd)
__device__ __align__(16) float  d_maskT[R*S];        // mask transposed [r][s]
__device__ __align__(16) float  d_qpart[R*NST*64];   // masked-pool partials
__device__ float d_t0part[R*NST];
__device__ float d_cntpart[R*NST];
__device__ __align__(16) float d_obuf[R*64];         // attention output per residue
__device__ float d_cg[64], d_dgb[64], d_ckv[16], d_dkv[16];
// padded-LDSM-layout bf16 weight tiles (hi/lo split)
__device__ __align__(16) uint32_t d_W1h[WPAD], d_W1l[WPAD];
__device__ __align__(16) uint32_t d_W2h[R*WPAD], d_W2l[R*WPAD];
__device__ __align__(16) uint32_t d_Wkvh[576], d_Wkvl[576];  // 16 rows x 144B

// ---------------- helpers ----------------
__device__ __forceinline__ uint32_t smem_u32(const void* p){
    uint32_t a;
    asm("{ .reg .u64 t; cvta.to.shared.u64 t, %1; cvt.u32.u64 %0, t; }" : "=r"(a) : "l"(p));
    return a;
}
__device__ __forceinline__ void ldsm4(uint32_t addr, uint32_t r[4]){
    asm volatile("ldmatrix.sync.aligned.m8n8.x4.shared.b16 {%0,%1,%2,%3}, [%4];"
        : "=r"(r[0]),"=r"(r[1]),"=r"(r[2]),"=r"(r[3]) : "r"(addr));
}
__device__ __forceinline__ void ldsm2(uint32_t addr, uint32_t r[2]){
    asm volatile("ldmatrix.sync.aligned.m8n8.x2.shared.b16 {%0,%1}, [%2];"
        : "=r"(r[0]),"=r"(r[1]) : "r"(addr));
}
__device__ __forceinline__ void mma16816(float c[4], const uint32_t a[4], uint32_t b0, uint32_t b1){
    asm volatile("mma.sync.aligned.m16n8k16.row.col.f32.bf16.bf16.f32 "
        "{%0,%1,%2,%3}, {%4,%5,%6,%7}, {%8,%9}, {%0,%1,%2,%3};"
        : "+f"(c[0]),"+f"(c[1]),"+f"(c[2]),"+f"(c[3])
        : "r"(a[0]),"r"(a[1]),"r"(a[2]),"r"(a[3]), "r"(b0),"r"(b1));
}
__device__ __forceinline__ void bsplit(float x, unsigned short& h, unsigned short& l){
    __nv_bfloat16 hb = __float2bfloat16_rn(x);
    float rrem = x - __bfloat162float(hb);
    __nv_bfloat16 lb = __float2bfloat16_rn(rrem);
    h = __bfloat16_as_ushort(hb); l = __bfloat16_as_ushort(lb);
}
__device__ __forceinline__ uint32_t bsplit2(float x0, float x1, uint32_t& lo){
    unsigned short h0,h1,l0,l1;
    bsplit(x0,h0,l0); bsplit(x1,h1,l1);
    lo = ((uint32_t)l1<<16)|l0;
    return ((uint32_t)h1<<16)|h0;
}

// ---------------- kernel 0: LN-folded weight precompute ----------------
__global__ void k0(const float* __restrict__ ln_g, const float* __restrict__ ln_b,
                   const float* __restrict__ Wk, const float* __restrict__ Wv,
                   const float* __restrict__ Wg, const float* __restrict__ bg){
    int t = threadIdx.x;
    for (int i=0;i<8;i++){
        int f = t + i*256;
        int j = f>>5, kp = f&31;
        float v0 = ln_g[2*kp]  *Wg[(2*kp)*64 + j];
        float v1 = ln_g[2*kp+1]*Wg[(2*kp+1)*64 + j];
        uint32_t lo, hi = bsplit2(v0, v1, lo);
        uint32_t w = (j*144 + 4*kp)>>2;
        d_W1h[w] = hi; d_W1l[w] = lo;
    }
    for (int i=t; i<512; i+=256){
        int c = i>>5, kp = i&31;
        int k0i = 2*kp, k1i = 2*kp+1;
        float w0 = (c<8) ? Wk[k0i*8+c] : Wv[k0i*8+(c-8)];
        float w1 = (c<8) ? Wk[k1i*8+c] : Wv[k1i*8+(c-8)];
        float v0 = ln_g[k0i]*w0, v1 = ln_g[k1i]*w1;
        uint32_t lo, hi = bsplit2(v0, v1, lo);
        uint32_t w = (c*144 + 4*kp)>>2;
        d_Wkvh[w] = hi; d_Wkvl[w] = lo;
    }
    if (t<64){
        float a=0.f, b=0.f;
        for (int k=0;k<64;k++){ a = fmaf(ln_g[k], Wg[k*64+t], a); b = fmaf(ln_b[k], Wg[k*64+t], b); }
        d_cg[t]=a; d_dgb[t]=b+bg[t];
    } else if (t<80){
        int c=t-64; float a=0.f, b=0.f;
        for (int k=0;k<64;k++){
            float wv = (c<8)?Wk[k*8+c]:Wv[k*8+(c-8)];
            a = fmaf(ln_g[k], wv, a); b = fmaf(ln_b[k], wv, b);
        }
        d_ckv[c]=a; d_dkv[c]=b;
    }
}

// ---------------- kernel A: stats + q-pool partials + mma kv GEMM ----------------
// grid: (NST, R) — s-tile fastest
__global__ void __launch_bounds__(256) kA(const float* __restrict__ M_raw,
                                          const float* __restrict__ M_mask){
    __shared__ __align__(16) float Xs[64*68];
    __shared__ __align__(16) char Ahi[64*144];
    __shared__ __align__(16) char Alo[64*144];
    __shared__ __align__(16) char Wh[16*144];
    __shared__ __align__(16) char Wl[16*144];
    __shared__ float mus[64], rss[64], msk[64], wrow[64];
    __shared__ float qp[4][64];
    __shared__ float sckv[16], sdkv[16];
    int r = blockIdx.y; int s0 = blockIdx.x*STILE; int t = threadIdx.x;
    int wid = t>>5, lane = t&31;

    if (t<16){ sckv[t]=d_ckv[t]; sdkv[t]=d_dkv[t]; }
    if (t<144){
        ((uint4*)Wh)[t] = ((const uint4*)d_Wkvh)[t];
        ((uint4*)Wl)[t] = ((const uint4*)d_Wkvl)[t];
    }

    #pragma unroll
    for (int i=0;i<4;i++){
        int f = t + i*256; int s = f>>4, c4 = f&15;
        float4 v = *(const float4*)(M_raw + ((size_t)(s0+s)*R + r)*DN + c4*4);
        *(float4*)(Xs + s*68 + c4*4) = v;
        uint32_t lo0, hi0 = bsplit2(v.x, v.y, lo0);
        uint32_t lo1, hi1 = bsplit2(v.z, v.w, lo1);
        uint32_t off = (uint32_t)s*144 + c4*8;
        *(uint2*)(Ahi + off) = make_uint2(hi0, hi1);
        *(uint2*)(Alo + off) = make_uint2(lo0, lo1);
    }
    __syncthreads();

    {
        int row = t>>2, p = t&3;
        float sm1=0.f, sq=0.f;
        #pragma unroll
        for (int i=0;i<4;i++){
            float4 v = *(float4*)(Xs + row*68 + p*16 + i*4);
            sm1 += (v.x+v.y)+(v.z+v.w);
            sq = fmaf(v.x,v.x,sq); sq=fmaf(v.y,v.y,sq); sq=fmaf(v.z,v.z,sq); sq=fmaf(v.w,v.w,sq);
        }
        sm1 += __shfl_xor_sync(0xffffffffu, sm1, 1); sq += __shfl_xor_sync(0xffffffffu, sq, 1);
        sm1 += __shfl_xor_sync(0xffffffffu, sm1, 2); sq += __shfl_xor_sync(0xffffffffu, sq, 2);
        if (p==0){
            float mu = sm1*(1.f/64.f);
            float var = fmaf(-mu, mu, sq*(1.f/64.f));
            float rstd = rsqrtf(var + 1e-5f);
            float m = M_mask[(size_t)(s0+row)*R + r];
            mus[row]=mu; rss[row]=rstd; msk[row]=m; wrow[row]=m*rstd;
            d_stats[(size_t)r*S + s0 + row] = make_float2(mu, rstd);
            d_maskT[(size_t)r*S + s0 + row] = m;
        }
    }
    __syncthreads();

    {
        int d = t&63, i4 = t>>6;
        float a = 0.f;
        #pragma unroll 4
        for (int rw = i4*16; rw < i4*16+16; rw++)
            a = fmaf(wrow[rw], Xs[rw*68+d], a);
        qp[i4][d] = a;
    }
    __syncthreads();
    if (t<64){
        d_qpart[((size_t)r*NST + blockIdx.x)*64 + t] = qp[0][t]+qp[1][t]+qp[2][t]+qp[3][t];
    } else if (t==64){
        float a=0.f; for (int rw=0;rw<64;rw++) a = fmaf(wrow[rw], mus[rw], a);
        d_t0part[r*NST + blockIdx.x] = a;
    } else if (t==65){
        float a=0.f; for (int rw=0;rw<64;rw++) a += msk[rw];
        d_cntpart[r*NST + blockIdx.x] = a;
    }

    { // kv GEMM via mma.sync
        int rowBase = (wid>>1)*16, colBase = (wid&1)*8;
        uint32_t aBaseH = smem_u32(Ahi), aBaseL = smem_u32(Alo);
        uint32_t bBaseH = smem_u32(Wh),  bBaseL = smem_u32(Wl);
        uint32_t aOff = (uint32_t)(rowBase + (lane&7) + ((lane>>3)&1)*8)*144 + ((lane>>4)&1)*16;
        uint32_t bOff = (uint32_t)(colBase + (lane&7))*144 + ((lane>>3)&1)*16;
        float c[4] = {0.f,0.f,0.f,0.f};
        #pragma unroll
        for (int k=0;k<4;k++){
            uint32_t kb = k*32;
            uint32_t ah[4], al[4], bh[2], bl[2];
            ldsm4(aBaseH + aOff + kb, ah);
            ldsm4(aBaseL + aOff + kb, al);
            ldsm2(bBaseH + bOff + kb, bh);
            ldsm2(bBaseL + bOff + kb, bl);
            mma16816(c, ah, bh[0], bh[1]);
            mma16816(c, ah, bl[0], bl[1]);
            mma16816(c, al, bh[0], bh[1]);
        }
        int sl0 = rowBase + (lane>>2), sl1 = sl0 + 8;
        int cc = colBase + (lane&3)*2;
        float f1a = rss[sl0], f0a = -rss[sl0]*mus[sl0];
        float f1b = rss[sl1], f0b = -rss[sl1]*mus[sl1];
        float2 o0, o1;
        o0.x = fmaf(f1a, c[0], fmaf(f0a, sckv[cc],   sdkv[cc]));
        o0.y = fmaf(f1a, c[1], fmaf(f0a, sckv[cc+1], sdkv[cc+1]));
        o1.x = fmaf(f1b, c[2], fmaf(f0b, sckv[cc],   sdkv[cc]));
        o1.y = fmaf(f1b, c[3], fmaf(f0b, sckv[cc+1], sdkv[cc+1]));
        *(float2*)(d_kv + ((size_t)r*S + s0 + sl0)*16 + cc) = o0;
        *(float2*)(d_kv + ((size_t)r*S + s0 + sl1)*16 + cc) = o1;
    }
}

// ---------------- kernel B: q + softmax attention -> o[r][64]; builds W2 tiles ----------------
__global__ void __launch_bounds__(256) kB(const float* __restrict__ Wq,
                                          const float* __restrict__ ln_g,
                                          const float* __restrict__ ln_b,
                                          const float* __restrict__ Wo){
    __shared__ float qa[64], qs[64];
    __shared__ float t0c[2];
    __shared__ float wred[8][80];
    __shared__ float mx[8];
    __shared__ float tot[72];
    __shared__ float oos[64];
    int r = blockIdx.x, t = threadIdx.x;
    int lane = t&31, w = t>>5;

    if (t<64){
        float a=0.f;
        #pragma unroll 4
        for (int ch=0; ch<NST; ch++) a += d_qpart[((size_t)r*NST+ch)*64 + t];
        qa[t] = a;
    } else if (t==64){
        float a=0.f,c=0.f;
        for (int ch=0; ch<NST; ch++){ a += d_t0part[r*NST+ch]; c += d_cntpart[r*NST+ch]; }
        t0c[0]=a; t0c[1]=c;
    }
    __syncthreads();
    if (t<64){
        float T0=t0c[0], cnt=t0c[1];
        qa[t] = (ln_g[t]*(qa[t]-T0) + ln_b[t]*cnt) * __fdividef(1.f, cnt + 1e-10f);
    }
    __syncthreads();
    if (t<64){
        float a=0.f;
        #pragma unroll
        for (int d=0; d<64; d++) a = fmaf(qa[d], Wq[d*64+t], a);
        qs[t] = a * 0.35355339059327373f;
    }
    __syncthreads();

    const float* kvr = d_kv + (size_t)r*S*16;
    const float* mr  = d_maskT + (size_t)r*S;

    float lmax[8];
    #pragma unroll
    for (int h=0;h<8;h++) lmax[h] = -3.0e38f;
    for (int it=0; it<8; it++){
        int s = t + it*256;
        float4 kk0 = *(const float4*)(kvr + s*16);
        float4 kk1 = *(const float4*)(kvr + s*16 + 4);
        float bias = 1e9f * (mr[s] - 1.f);
        #pragma unroll
        for (int h=0;h<8;h++){
            const float* q = qs + h*8;
            float l = bias;
            l=fmaf(q[0],kk0.x,l); l=fmaf(q[1],kk0.y,l); l=fmaf(q[2],kk0.z,l); l=fmaf(q[3],kk0.w,l);
            l=fmaf(q[4],kk1.x,l); l=fmaf(q[5],kk1.y,l); l=fmaf(q[6],kk1.z,l); l=fmaf(q[7],kk1.w,l);
            lmax[h] = fmaxf(lmax[h], l);
        }
    }
    #pragma unroll
    for (int h=0;h<8;h++){
        float v = lmax[h];
        v = fmaxf(v, __shfl_xor_sync(0xffffffffu,v,16));
        v = fmaxf(v, __shfl_xor_sync(0xffffffffu,v,8));
        v = fmaxf(v, __shfl_xor_sync(0xffffffffu,v,4));
        v = fmaxf(v, __shfl_xor_sync(0xffffffffu,v,2));
        v = fmaxf(v, __shfl_xor_sync(0xffffffffu,v,1));
        if (lane==0) wred[w][h] = v;
    }
    __syncthreads();
    if (t<8){
        float v = wred[0][t];
        #pragma unroll
        for (int i=1;i<8;i++) v = fmaxf(v, wred[i][t]);
        mx[t]=v;
    }
    __syncthreads();

    float acc[64];
    #pragma unroll
    for (int i=0;i<64;i++) acc[i]=0.f;
    float esum[8], mxr[8];
    #pragma unroll
    for (int h=0;h<8;h++){ esum[h]=0.f; mxr[h]=mx[h]; }

    for (int it=0; it<8; it++){
        int s = t + it*256;
        float4 kk0 = *(const float4*)(kvr + s*16);
        float4 kk1 = *(const float4*)(kvr + s*16 + 4);
        float4 v0 = *(const float4*)(kvr + s*16 + 8);
        float4 v1 = *(const float4*)(kvr + s*16 + 12);
        float bias = 1e9f*(mr[s]-1.f);
        #pragma unroll
        for (int h=0;h<8;h++){
            const float* q = qs + h*8;
            float l = bias;
            l=fmaf(q[0],kk0.x,l); l=fmaf(q[1],kk0.y,l); l=fmaf(q[2],kk0.z,l); l=fmaf(q[3],kk0.w,l);
            l=fmaf(q[4],kk1.x,l); l=fmaf(q[5],kk1.y,l); l=fmaf(q[6],kk1.z,l); l=fmaf(q[7],kk1.w,l);
            float e = __expf(l - mxr[h]);
            esum[h] += e;
            acc[h*8+0]=fmaf(e,v0.x,acc[h*8+0]); acc[h*8+1]=fmaf(e,v0.y,acc[h*8+1]);
            acc[h*8+2]=fmaf(e,v0.z,acc[h*8+2]); acc[h*8+3]=fmaf(e,v0.w,acc[h*8+3]);
            acc[h*8+4]=fmaf(e,v1.x,acc[h*8+4]); acc[h*8+5]=fmaf(e,v1.y,acc[h*8+5]);
            acc[h*8+6]=fmaf(e,v1.z,acc[h*8+6]); acc[h*8+7]=fmaf(e,v1.w,acc[h*8+7]);
        }
    }
    #pragma unroll
    for (int i=0;i<64;i++){
        float v = acc[i];
        v += __shfl_xor_sync(0xffffffffu,v,16); v += __shfl_xor_sync(0xffffffffu,v,8);
        v += __shfl_xor_sync(0xffffffffu,v,4);  v += __shfl_xor_sync(0xffffffffu,v,2);
        v += __shfl_xor_sync(0xffffffffu,v,1);
        acc[i]=v;
    }
    #pragma unroll
    for (int h=0;h<8;h++){
        float v = esum[h];
        v += __shfl_xor_sync(0xffffffffu,v,16); v += __shfl_xor_sync(0xffffffffu,v,8);
        v += __shfl_xor_sync(0xffffffffu,v,4);  v += __shfl_xor_sync(0xffffffffu,v,2);
        v += __shfl_xor_sync(0xffffffffu,v,1);
        esum[h]=v;
    }
    if (lane==0){
        #pragma unroll
        for (int i=0;i<64;i++) wred[w][i]=acc[i];
        #pragma unroll
        for (int h=0;h<8;h++) wred[w][64+h]=esum[h];
    }
    __syncthreads();
    if (t<72){
        float v=0.f;
        #pragma unroll
        for (int i=0;i<8;i++) v += wred[i][t];
        tot[t]=v;
    }
    __syncthreads();
    if (t<64){
        float o = __fdividef(tot[t], tot[64+(t>>3)]);
        d_obuf[r*64+t] = o;
        oos[t] = o;
    }
    __syncthreads();

    uint32_t* W2h = d_W2h + (size_t)r*WPAD;
    uint32_t* W2l = d_W2l + (size_t)r*WPAD;
    #pragma unroll
    for (int i=0;i<8;i++){
        int f = t + i*256;
        int d = f>>5, jp = f&31;
        float v0 = Wo[(2*jp)*64 + d]  *oos[2*jp];
        float v1 = Wo[(2*jp+1)*64 + d]*oos[2*jp+1];
        uint32_t lo, hi = bsplit2(v0, v1, lo);
        uint32_t w = (d*144 + 4*jp)>>2;
        W2h[w] = hi; W2l[w] = lo;
    }
}

// ---------------- kernel C: mma.sync bf16-split gate/output GEMMs ----------------
// 128 threads, warp tile 32 rows x 64 cols (exclusive row ownership, deduped B frags).
#define KC_STR    144
#define OFF_AHI   0
#define OFF_ALO   18432
#define OFF_WH    36864
#define OFF_WL    46080
#define OFF_STATS 55296
#define OFF_CG    56320
#define OFF_DGB   56576
#define OFF_BO    56832
#define SMEM_KC   57088

// warp computes rows [rowBase, rowBase+32) x all 64 cols
__device__ __forceinline__ void gemm_mma64(uint32_t aHi, uint32_t aLo,
                                           uint32_t bHi, uint32_t bLo,
                                           int lane, int rowBase,
                                           float acc[2][8][4]){
    uint32_t aRowOff = (uint32_t)((lane&7) + ((lane>>3)&1)*8) * KC_STR + ((lane>>4)&1)*16;
    uint32_t bRowOff = (uint32_t)((lane&7) + ((lane>>4)&1)*8) * KC_STR + ((lane>>3)&1)*16;
    #pragma unroll
    for (int k=0;k<4;k++){
        uint32_t kb = k*32;
        uint32_t ah[2][4], al[2][4];
        #pragma unroll
        for (int mt=0;mt<2;mt++){
            uint32_t addr = aHi + (uint32_t)(rowBase + mt*16)*KC_STR + aRowOff + kb;
            ldsm4(addr, ah[mt]);
            ldsm4(addr + (aLo - aHi), al[mt]);
        }
        #pragma unroll
        for (int ng=0; ng<4; ng++){
            uint32_t addr = bHi + (uint32_t)(ng*16)*KC_STR + bRowOff + kb;
            uint32_t bh[4], bl[4];
            ldsm4(addr, bh);
            ldsm4(addr + (bLo - bHi), bl);
            #pragma unroll
            for (int half=0; half<2; half++){
                int n = ng*2 + half;
                #pragma unroll
                for (int mt=0;mt<2;mt++){
                    mma16816(acc[mt][n], ah[mt], bh[half*2], bh[half*2+1]);
                    mma16816(acc[mt][n], ah[mt], bl[half*2], bl[half*2+1]);
                    mma16816(acc[mt][n], al[mt], bh[half*2], bh[half*2+1]);
                }
            }
        }
    }
}

__global__ void __launch_bounds__(128, 4) kC(const float* __restrict__ M_raw,
                                             const float* __restrict__ bo,
                                             float* __restrict__ outp){
    extern __shared__ __align__(1024) char sm[];
    uint32_t smb = smem_u32(sm);
    int r = blockIdx.y; int s0 = blockIdx.x*SKC; int t = threadIdx.x;
    int wid = t>>5, lane = t&31;

    float* cgp  = (float*)(sm + OFF_CG);
    float* dgbp = (float*)(sm + OFF_DGB);
    float* bop  = (float*)(sm + OFF_BO);
    float2* stp = (float2*)(sm + OFF_STATS);

    // ---- prologue: A tiles + W1 + constants ----
    #pragma unroll
    for (int i=0;i<16;i++){
        int f = t + i*128; int row = f>>4, c4 = f&15;
        float4 v = *(const float4*)(M_raw + ((size_t)(s0+row)*R + r)*DN + c4*4);
        uint32_t lo0, hi0 = bsplit2(v.x, v.y, lo0);
        uint32_t lo1, hi1 = bsplit2(v.z, v.w, lo1);
        uint32_t off = (uint32_t)row*KC_STR + c4*8;
        *(uint2*)(sm + OFF_AHI + off) = make_uint2(hi0, hi1);
        *(uint2*)(sm + OFF_ALO + off) = make_uint2(lo0, lo1);
    }
    {
        const uint4* s1h = (const uint4*)d_W1h;
        const uint4* s1l = (const uint4*)d_W1l;
        uint4* th = (uint4*)(sm + OFF_WH);
        uint4* tl = (uint4*)(sm + OFF_WL);
        #pragma unroll
        for (int i=0;i<5;i++){
            int f = t + i*128;
            if (f < 576){ th[f]=s1h[f]; tl[f]=s1l[f]; }
        }
    }
    stp[t] = d_stats[(size_t)r*S + s0 + t];       // 128 threads = 128 rows
    if (t<64){ cgp[t]=d_cg[t]; dgbp[t]=d_dgb[t]; bop[t]=bo[t]; }
    __syncthreads();

    int rowBase = wid*32;
    float acc[2][8][4];
    #pragma unroll
    for (int mt=0;mt<2;mt++)
        #pragma unroll
        for (int n=0;n<8;n++)
            #pragma unroll
            for (int c=0;c<4;c++) acc[mt][n][c]=0.f;

    // ---- GEMM1: X @ W1 ----
    gemm_mma64(smb+OFF_AHI, smb+OFF_ALO, smb+OFF_WH, smb+OFF_WL, lane, rowBase, acc);

    // ---- gate: LN fold + sigmoid in regs; write G into OWN A rows (exclusive) ----
    #pragma unroll
    for (int mt=0;mt<2;mt++){
        int row0 = rowBase + mt*16 + (lane>>2);
        int row1 = row0 + 8;
        float2 st0 = stp[row0], st1 = stp[row1];
        float f1a = st0.y, f0a = -st0.y*st0.x;
        float f1b = st1.y, f0b = -st1.y*st1.x;
        #pragma unroll
        for (int n=0;n<8;n++){
            int j = n*8 + (lane&3)*2;
            float cg0=cgp[j], cg1=cgp[j+1], db0=dgbp[j], db1=dgbp[j+1];
            float z00 = fmaf(f1a, acc[mt][n][0], fmaf(f0a, cg0, db0));
            float z01 = fmaf(f1a, acc[mt][n][1], fmaf(f0a, cg1, db1));
            float z10 = fmaf(f1b, acc[mt][n][2], fmaf(f0b, cg0, db0));
            float z11 = fmaf(f1b, acc[mt][n][3], fmaf(f0b, cg1, db1));
            float g00 = __fdividef(1.f, 1.f + __expf(-z00));
            float g01 = __fdividef(1.f, 1.f + __expf(-z01));
            float g10 = __fdividef(1.f, 1.f + __expf(-z10));
            float g11 = __fdividef(1.f, 1.f + __expf(-z11));
            uint32_t lo, hi;
            hi = bsplit2(g00, g01, lo);
            uint32_t off0 = (uint32_t)row0*KC_STR + 2*j;
            *(uint32_t*)(sm + OFF_AHI + off0) = hi;
            *(uint32_t*)(sm + OFF_ALO + off0) = lo;
            hi = bsplit2(g10, g11, lo);
            uint32_t off1 = (uint32_t)row1*KC_STR + 2*j;
            *(uint32_t*)(sm + OFF_AHI + off1) = hi;
            *(uint32_t*)(sm + OFF_ALO + off1) = lo;
        }
    }
    __syncthreads();   // all warps done with W1 reads (and G writes, own-rows only)

    // ---- overwrite W slot with W2 ----
    {
        const uint4* s2h = (const uint4*)(d_W2h + (size_t)r*WPAD);
        const uint4* s2l = (const uint4*)(d_W2l + (size_t)r*WPAD);
        uint4* th = (uint4*)(sm + OFF_WH);
        uint4* tl = (uint4*)(sm + OFF_WL);
        #pragma unroll
        for (int i=0;i<5;i++){
            int f = t + i*128;
            if (f < 576){ th[f]=s2h[f]; tl[f]=s2l[f]; }
        }
    }
    __syncthreads();

    #pragma unroll
    for (int mt=0;mt<2;mt++)
        #pragma unroll
        for (int n=0;n<8;n++)
            #pragma unroll
            for (int c=0;c<4;c++) acc[mt][n][c]=0.f;

    // ---- GEMM2: G @ W2 ----
    gemm_mma64(smb+OFF_AHI, smb+OFF_ALO, smb+OFF_WH, smb+OFF_WL, lane, rowBase, acc);

    // ---- epilogue: + bo + residual (re-read M_raw, L2-hot) -> gmem ----
    #pragma unroll
    for (int mt=0;mt<2;mt++){
        int row0 = rowBase + mt*16 + (lane>>2);
        int row1 = row0 + 8;
        const float* xb0 = M_raw + ((size_t)(s0+row0)*R + r)*DN;
        const float* xb1 = M_raw + ((size_t)(s0+row1)*R + r)*DN;
        float* ob0 = outp + ((size_t)(s0+row0)*R + r)*DN;
        float* ob1 = outp + ((size_t)(s0+row1)*R + r)*DN;
        #pragma unroll
        for (int n=0;n<8;n++){
            int j = n*8 + (lane&3)*2;
            float b0v=bop[j], b1v=bop[j+1];
            float2 x0 = *(const float2*)(xb0 + j);
            float2 x1 = *(const float2*)(xb1 + j);
            *(float2*)(ob0 + j) = make_float2(acc[mt][n][0]+b0v+x0.x, acc[mt][n][1]+b1v+x0.y);
            *(float2*)(ob1 + j) = make_float2(acc[mt][n][2]+b0v+x1.x, acc[mt][n][3]+b1v+x1.y);
        }
    }
}

// ---------------- launch ----------------
extern "C" void kernel_launch(void* const* d_in, const int* in_sizes, int n_in,
                              void* d_out, int out_size) {
    const float* M_raw  = (const float*)d_in[0];
    const float* M_mask = (const float*)d_in[1];
    const float* ln_g   = (const float*)d_in[2];
    const float* ln_b   = (const float*)d_in[3];
    const float* Wq     = (const float*)d_in[4];
    const float* Wk     = (const float*)d_in[5];
    const float* Wv     = (const float*)d_in[6];
    const float* Wg     = (const float*)d_in[7];
    const float* bg     = (const float*)d_in[8];
    const float* Wo     = (const float*)d_in[9];
    const float* bo     = (const float*)d_in[10];
    float* outp = (float*)d_out;

    static bool attr_done = false;
    if (!attr_done) {
        cudaFuncSetAttribute(kC, cudaFuncAttributeMaxDynamicSharedMemorySize, SMEM_KC);
        attr_done = true;
    }

    k0<<<1, 256>>>(ln_g, ln_b, Wk, Wv, Wg, bg);
    kA<<<dim3(NST, R), 256>>>(M_raw, M_mask);
    kB<<<R, 256>>>(Wq, ln_g, ln_b, Wo);
    kC<<<dim3(NKC, R), 128, SMEM_KC>>>(M_raw, bo, outp);
}

// round 13
// speedup vs baseline: 1.0200x; 1.0200x over previous
#include <cuda_runtime.h>
#include <cuda_bf16.h>
#include <math.h>
#include <stdint.h>

#define S 2048
#define R 384
#define DN 64
#define STILE 64
#define NST (S/STILE)   // 32 tiles for kA
#define SKC 128         // s-rows per kC block
#define NKC (S/SKC)     // 16
#define WPAD 2304       // uint32 words per padded 64x144B weight tile

// ---------------- scratch (static device memory; no allocations) ----------------
__device__ __align__(16) float  d_kv[R*S*16];        // per (r,s): k[8], v[8]
__device__ __align__(16) float2 d_stats[R*S];        // per (r,s): (mu, rstd)
__device__ __align__(16) float  d_maskT[R*S];        // mask transposed [r][s]
__device__ __align__(16) float  d_qpart[R*NST*64];   // masked-pool partials
__device__ float d_t0part[R*NST];
__device__ float d_cntpart[R*NST];
__device__ __align__(16) float d_obuf[R*64];         // attention output per residue
__device__ float d_cg[64], d_dgb[64], d_ckv[16], d_dkv[16];
// padded-LDSM-layout bf16 weight tiles (hi/lo split)
__device__ __align__(16) uint32_t d_W1h[WPAD], d_W1l[WPAD];
__device__ __align__(16) uint32_t d_W2h[R*WPAD], d_W2l[R*WPAD];
__device__ __align__(16) uint32_t d_Wkvh[576], d_Wkvl[576];  // 16 rows x 144B

// ---------------- helpers ----------------
__device__ __forceinline__ uint32_t smem_u32(const void* p){
    uint32_t a;
    asm("{ .reg .u64 t; cvta.to.shared.u64 t, %1; cvt.u32.u64 %0, t; }" : "=r"(a) : "l"(p));
    return a;
}
__device__ __forceinline__ void ldsm4(uint32_t addr, uint32_t r[4]){
    asm volatile("ldmatrix.sync.aligned.m8n8.x4.shared.b16 {%0,%1,%2,%3}, [%4];"
        : "=r"(r[0]),"=r"(r[1]),"=r"(r[2]),"=r"(r[3]) : "r"(addr));
}
__device__ __forceinline__ void ldsm2(uint32_t addr, uint32_t r[2]){
    asm volatile("ldmatrix.sync.aligned.m8n8.x2.shared.b16 {%0,%1}, [%2];"
        : "=r"(r[0]),"=r"(r[1]) : "r"(addr));
}
__device__ __forceinline__ void mma16816(float c[4], const uint32_t a[4], uint32_t b0, uint32_t b1){
    asm volatile("mma.sync.aligned.m16n8k16.row.col.f32.bf16.bf16.f32 "
        "{%0,%1,%2,%3}, {%4,%5,%6,%7}, {%8,%9}, {%0,%1,%2,%3};"
        : "+f"(c[0]),"+f"(c[1]),"+f"(c[2]),"+f"(c[3])
        : "r"(a[0]),"r"(a[1]),"r"(a[2]),"r"(a[3]), "r"(b0),"r"(b1));
}
__device__ __forceinline__ void bsplit(float x, unsigned short& h, unsigned short& l){
    __nv_bfloat16 hb = __float2bfloat16_rn(x);
    float rrem = x - __bfloat162float(hb);
    __nv_bfloat16 lb = __float2bfloat16_rn(rrem);
    h = __bfloat16_as_ushort(hb); l = __bfloat16_as_ushort(lb);
}
__device__ __forceinline__ uint32_t bsplit2(float x0, float x1, uint32_t& lo){
    unsigned short h0,h1,l0,l1;
    bsplit(x0,h0,l0); bsplit(x1,h1,l1);
    lo = ((uint32_t)l1<<16)|l0;
    return ((uint32_t)h1<<16)|h0;
}

// ---------------- kernel 0: LN-folded weight precompute ----------------
__global__ void k0(const float* __restrict__ ln_g, const float* __restrict__ ln_b,
                   const float* __restrict__ Wk, const float* __restrict__ Wv,
                   const float* __restrict__ Wg, const float* __restrict__ bg){
    int t = threadIdx.x;
    for (int i=0;i<8;i++){
        int f = t + i*256;
        int j = f>>5, kp = f&31;
        float v0 = ln_g[2*kp]  *Wg[(2*kp)*64 + j];
        float v1 = ln_g[2*kp+1]*Wg[(2*kp+1)*64 + j];
        uint32_t lo, hi = bsplit2(v0, v1, lo);
        uint32_t w = (j*144 + 4*kp)>>2;
        d_W1h[w] = hi; d_W1l[w] = lo;
    }
    for (int i=t; i<512; i+=256){
        int c = i>>5, kp = i&31;
        int k0i = 2*kp, k1i = 2*kp+1;
        float w0 = (c<8) ? Wk[k0i*8+c] : Wv[k0i*8+(c-8)];
        float w1 = (c<8) ? Wk[k1i*8+c] : Wv[k1i*8+(c-8)];
        float v0 = ln_g[k0i]*w0, v1 = ln_g[k1i]*w1;
        uint32_t lo, hi = bsplit2(v0, v1, lo);
        uint32_t w = (c*144 + 4*kp)>>2;
        d_Wkvh[w] = hi; d_Wkvl[w] = lo;
    }
    if (t<64){
        float a=0.f, b=0.f;
        for (int k=0;k<64;k++){ a = fmaf(ln_g[k], Wg[k*64+t], a); b = fmaf(ln_b[k], Wg[k*64+t], b); }
        d_cg[t]=a; d_dgb[t]=b+bg[t];
    } else if (t<80){
        int c=t-64; float a=0.f, b=0.f;
        for (int k=0;k<64;k++){
            float wv = (c<8)?Wk[k*8+c]:Wv[k*8+(c-8)];
            a = fmaf(ln_g[k], wv, a); b = fmaf(ln_b[k], wv, b);
        }
        d_ckv[c]=a; d_dkv[c]=b;
    }
}

// ---------------- kernel A: stats + q-pool partials + mma kv GEMM ----------------
// grid: (NST, R) — s-tile fastest
__global__ void __launch_bounds__(256) kA(const float* __restrict__ M_raw,
                                          const float* __restrict__ M_mask){
    __shared__ __align__(16) float Xs[64*68];
    __shared__ __align__(16) char Ahi[64*144];
    __shared__ __align__(16) char Alo[64*144];
    __shared__ __align__(16) char Wh[16*144];
    __shared__ __align__(16) char Wl[16*144];
    __shared__ float mus[64], rss[64], msk[64], wrow[64];
    __shared__ float qp[4][64];
    __shared__ float sckv[16], sdkv[16];
    int r = blockIdx.y; int s0 = blockIdx.x*STILE; int t = threadIdx.x;
    int wid = t>>5, lane = t&31;

    if (t<16){ sckv[t]=d_ckv[t]; sdkv[t]=d_dkv[t]; }
    if (t<144){
        ((uint4*)Wh)[t] = ((const uint4*)d_Wkvh)[t];
        ((uint4*)Wl)[t] = ((const uint4*)d_Wkvl)[t];
    }

    #pragma unroll
    for (int i=0;i<4;i++){
        int f = t + i*256; int s = f>>4, c4 = f&15;
        float4 v = *(const float4*)(M_raw + ((size_t)(s0+s)*R + r)*DN + c4*4);
        *(float4*)(Xs + s*68 + c4*4) = v;
        uint32_t lo0, hi0 = bsplit2(v.x, v.y, lo0);
        uint32_t lo1, hi1 = bsplit2(v.z, v.w, lo1);
        uint32_t off = (uint32_t)s*144 + c4*8;
        *(uint2*)(Ahi + off) = make_uint2(hi0, hi1);
        *(uint2*)(Alo + off) = make_uint2(lo0, lo1);
    }
    __syncthreads();

    {
        int row = t>>2, p = t&3;
        float sm1=0.f, sq=0.f;
        #pragma unroll
        for (int i=0;i<4;i++){
            float4 v = *(float4*)(Xs + row*68 + p*16 + i*4);
            sm1 += (v.x+v.y)+(v.z+v.w);
            sq = fmaf(v.x,v.x,sq); sq=fmaf(v.y,v.y,sq); sq=fmaf(v.z,v.z,sq); sq=fmaf(v.w,v.w,sq);
        }
        sm1 += __shfl_xor_sync(0xffffffffu, sm1, 1); sq += __shfl_xor_sync(0xffffffffu, sq, 1);
        sm1 += __shfl_xor_sync(0xffffffffu, sm1, 2); sq += __shfl_xor_sync(0xffffffffu, sq, 2);
        if (p==0){
            float mu = sm1*(1.f/64.f);
            float var = fmaf(-mu, mu, sq*(1.f/64.f));
            float rstd = rsqrtf(var + 1e-5f);
            float m = M_mask[(size_t)(s0+row)*R + r];
            mus[row]=mu; rss[row]=rstd; msk[row]=m; wrow[row]=m*rstd;
            d_stats[(size_t)r*S + s0 + row] = make_float2(mu, rstd);
            d_maskT[(size_t)r*S + s0 + row] = m;
        }
    }
    __syncthreads();

    {
        int d = t&63, i4 = t>>6;
        float a = 0.f;
        #pragma unroll 4
        for (int rw = i4*16; rw < i4*16+16; rw++)
            a = fmaf(wrow[rw], Xs[rw*68+d], a);
        qp[i4][d] = a;
    }
    __syncthreads();
    if (t<64){
        d_qpart[((size_t)r*NST + blockIdx.x)*64 + t] = qp[0][t]+qp[1][t]+qp[2][t]+qp[3][t];
    } else if (t==64){
        float a=0.f; for (int rw=0;rw<64;rw++) a = fmaf(wrow[rw], mus[rw], a);
        d_t0part[r*NST + blockIdx.x] = a;
    } else if (t==65){
        float a=0.f; for (int rw=0;rw<64;rw++) a += msk[rw];
        d_cntpart[r*NST + blockIdx.x] = a;
    }

    { // kv GEMM via mma.sync
        int rowBase = (wid>>1)*16, colBase = (wid&1)*8;
        uint32_t aBaseH = smem_u32(Ahi), aBaseL = smem_u32(Alo);
        uint32_t bBaseH = smem_u32(Wh),  bBaseL = smem_u32(Wl);
        uint32_t aOff = (uint32_t)(rowBase + (lane&7) + ((lane>>3)&1)*8)*144 + ((lane>>4)&1)*16;
        uint32_t bOff = (uint32_t)(colBase + (lane&7))*144 + ((lane>>3)&1)*16;
        float c[4] = {0.f,0.f,0.f,0.f};
        #pragma unroll
        for (int k=0;k<4;k++){
            uint32_t kb = k*32;
            uint32_t ah[4], al[4], bh[2], bl[2];
            ldsm4(aBaseH + aOff + kb, ah);
            ldsm4(aBaseL + aOff + kb, al);
            ldsm2(bBaseH + bOff + kb, bh);
            ldsm2(bBaseL + bOff + kb, bl);
            mma16816(c, ah, bh[0], bh[1]);
            mma16816(c, ah, bl[0], bl[1]);
            mma16816(c, al, bh[0], bh[1]);
        }
        int sl0 = rowBase + (lane>>2), sl1 = sl0 + 8;
        int cc = colBase + (lane&3)*2;
        float f1a = rss[sl0], f0a = -rss[sl0]*mus[sl0];
        float f1b = rss[sl1], f0b = -rss[sl1]*mus[sl1];
        float2 o0, o1;
        o0.x = fmaf(f1a, c[0], fmaf(f0a, sckv[cc],   sdkv[cc]));
        o0.y = fmaf(f1a, c[1], fmaf(f0a, sckv[cc+1], sdkv[cc+1]));
        o1.x = fmaf(f1b, c[2], fmaf(f0b, sckv[cc],   sdkv[cc]));
        o1.y = fmaf(f1b, c[3], fmaf(f0b, sckv[cc+1], sdkv[cc+1]));
        *(float2*)(d_kv + ((size_t)r*S + s0 + sl0)*16 + cc) = o0;
        *(float2*)(d_kv + ((size_t)r*S + s0 + sl1)*16 + cc) = o1;
    }
}

// ---------------- kernel B: one-pass online-softmax attention -> o[r][64]; builds W2 ----------------
__global__ void __launch_bounds__(256) kB(const float* __restrict__ Wq,
                                          const float* __restrict__ ln_g,
                                          const float* __restrict__ ln_b,
                                          const float* __restrict__ Wo){
    __shared__ float qa[64], qs[64];
    __shared__ float t0c[2];
    __shared__ float wred[8][80];
    __shared__ float mx[8];
    __shared__ float tot[72];
    __shared__ float oos[64];
    int r = blockIdx.x, t = threadIdx.x;
    int lane = t&31, w = t>>5;

    if (t<64){
        float a=0.f;
        #pragma unroll 4
        for (int ch=0; ch<NST; ch++) a += d_qpart[((size_t)r*NST+ch)*64 + t];
        qa[t] = a;
    } else if (t==64){
        float a=0.f,c=0.f;
        for (int ch=0; ch<NST; ch++){ a += d_t0part[r*NST+ch]; c += d_cntpart[r*NST+ch]; }
        t0c[0]=a; t0c[1]=c;
    }
    __syncthreads();
    if (t<64){
        float T0=t0c[0], cnt=t0c[1];
        qa[t] = (ln_g[t]*(qa[t]-T0) + ln_b[t]*cnt) * __fdividef(1.f, cnt + 1e-10f);
    }
    __syncthreads();
    if (t<64){
        float a=0.f;
        #pragma unroll
        for (int d=0; d<64; d++) a = fmaf(qa[d], Wq[d*64+t], a);
        qs[t] = a * 0.35355339059327373f;
    }
    __syncthreads();

    const float* kvr = d_kv + (size_t)r*S*16;
    const float* mr  = d_maskT + (size_t)r*S;

    // ---- single pass: thread-local online softmax ----
    float lmax[8], esum[8], acc[64];
    #pragma unroll
    for (int h=0;h<8;h++){ lmax[h] = -3.0e38f; esum[h]=0.f; }
    #pragma unroll
    for (int i=0;i<64;i++) acc[i]=0.f;

    for (int it=0; it<8; it++){
        int s = t + it*256;
        float4 kk0 = *(const float4*)(kvr + s*16);
        float4 kk1 = *(const float4*)(kvr + s*16 + 4);
        float4 v0  = *(const float4*)(kvr + s*16 + 8);
        float4 v1  = *(const float4*)(kvr + s*16 + 12);
        float bias = 1e9f*(mr[s]-1.f);
        #pragma unroll
        for (int h=0;h<8;h++){
            const float* q = qs + h*8;
            float l = bias;
            l=fmaf(q[0],kk0.x,l); l=fmaf(q[1],kk0.y,l); l=fmaf(q[2],kk0.z,l); l=fmaf(q[3],kk0.w,l);
            l=fmaf(q[4],kk1.x,l); l=fmaf(q[5],kk1.y,l); l=fmaf(q[6],kk1.z,l); l=fmaf(q[7],kk1.w,l);
            if (l > lmax[h]){
                float sc = __expf(lmax[h] - l);   // exp(-inf)=0 on first hit
                esum[h] *= sc;
                #pragma unroll
                for (int c=0;c<8;c++) acc[h*8+c] *= sc;
                lmax[h] = l;
            }
            float e = __expf(l - lmax[h]);
            esum[h] += e;
            acc[h*8+0]=fmaf(e,v0.x,acc[h*8+0]); acc[h*8+1]=fmaf(e,v0.y,acc[h*8+1]);
            acc[h*8+2]=fmaf(e,v0.z,acc[h*8+2]); acc[h*8+3]=fmaf(e,v0.w,acc[h*8+3]);
            acc[h*8+4]=fmaf(e,v1.x,acc[h*8+4]); acc[h*8+5]=fmaf(e,v1.y,acc[h*8+5]);
            acc[h*8+6]=fmaf(e,v1.z,acc[h*8+6]); acc[h*8+7]=fmaf(e,v1.w,acc[h*8+7]);
        }
    }

    // ---- block max per head ----
    #pragma unroll
    for (int h=0;h<8;h++){
        float v = lmax[h];
        v = fmaxf(v, __shfl_xor_sync(0xffffffffu,v,16));
        v = fmaxf(v, __shfl_xor_sync(0xffffffffu,v,8));
        v = fmaxf(v, __shfl_xor_sync(0xffffffffu,v,4));
        v = fmaxf(v, __shfl_xor_sync(0xffffffffu,v,2));
        v = fmaxf(v, __shfl_xor_sync(0xffffffffu,v,1));
        if (lane==0) wred[w][h] = v;
    }
    __syncthreads();
    if (t<8){
        float v = wred[0][t];
        #pragma unroll
        for (int i=1;i<8;i++) v = fmaxf(v, wred[i][t]);
        mx[t]=v;
    }
    __syncthreads();

    // ---- rescale thread-local partials to global max ----
    #pragma unroll
    for (int h=0;h<8;h++){
        float f = __expf(lmax[h] - mx[h]);
        esum[h] *= f;
        #pragma unroll
        for (int c=0;c<8;c++) acc[h*8+c] *= f;
    }

    // ---- cross-thread sums ----
    #pragma unroll
    for (int i=0;i<64;i++){
        float v = acc[i];
        v += __shfl_xor_sync(0xffffffffu,v,16); v += __shfl_xor_sync(0xffffffffu,v,8);
        v += __shfl_xor_sync(0xffffffffu,v,4);  v += __shfl_xor_sync(0xffffffffu,v,2);
        v += __shfl_xor_sync(0xffffffffu,v,1);
        acc[i]=v;
    }
    #pragma unroll
    for (int h=0;h<8;h++){
        float v = esum[h];
        v += __shfl_xor_sync(0xffffffffu,v,16); v += __shfl_xor_sync(0xffffffffu,v,8);
        v += __shfl_xor_sync(0xffffffffu,v,4);  v += __shfl_xor_sync(0xffffffffu,v,2);
        v += __shfl_xor_sync(0xffffffffu,v,1);
        esum[h]=v;
    }
    __syncthreads();  // wred reuse
    if (lane==0){
        #pragma unroll
        for (int i=0;i<64;i++) wred[w][i]=acc[i];
        #pragma unroll
        for (int h=0;h<8;h++) wred[w][64+h]=esum[h];
    }
    __syncthreads();
    if (t<72){
        float v=0.f;
        #pragma unroll
        for (int i=0;i<8;i++) v += wred[i][t];
        tot[t]=v;
    }
    __syncthreads();
    if (t<64){
        float o = __fdividef(tot[t], tot[64+(t>>3)]);
        d_obuf[r*64+t] = o;
        oos[t] = o;
    }
    __syncthreads();

    uint32_t* W2h = d_W2h + (size_t)r*WPAD;
    uint32_t* W2l = d_W2l + (size_t)r*WPAD;
    #pragma unroll
    for (int i=0;i<8;i++){
        int f = t + i*256;
        int d = f>>5, jp = f&31;
        float v0 = Wo[(2*jp)*64 + d]  *oos[2*jp];
        float v1 = Wo[(2*jp+1)*64 + d]*oos[2*jp+1];
        uint32_t lo, hi = bsplit2(v0, v1, lo);
        uint32_t w2 = (d*144 + 4*jp)>>2;
        W2h[w2] = hi; W2l[w2] = lo;
    }
}

// ---------------- kernel C: mma.sync bf16-split gate/output GEMMs (R10 config) ----------------
#define KC_STR    144
#define OFF_AHI   0
#define OFF_ALO   18432
#define OFF_WH    36864
#define OFF_WL    46080
#define OFF_STATS 55296
#define OFF_CG    56320
#define OFF_DGB   56576
#define OFF_BO    56832
#define SMEM_KC   57088

__device__ __forceinline__ void gemm_mma(uint32_t aHi, uint32_t aLo,
                                         uint32_t bHi, uint32_t bLo,
                                         int lane, int rowBase, int colBase,
                                         float acc[2][4][4]){
    uint32_t aRowOff = (uint32_t)((lane&7) + ((lane>>3)&1)*8) * KC_STR + ((lane>>4)&1)*16;
    uint32_t bRowOff = (uint32_t)((lane&7) + ((lane>>4)&1)*8) * KC_STR + ((lane>>3)&1)*16;
    #pragma unroll
    for (int k=0;k<4;k++){
        uint32_t kb = k*32;
        uint32_t ah[2][4], al[2][4];
        #pragma unroll
        for (int mt=0;mt<2;mt++){
            uint32_t addr = aHi + (uint32_t)(rowBase + mt*16)*KC_STR + aRowOff + kb;
            ldsm4(addr, ah[mt]);
            ldsm4(addr + (aLo - aHi), al[mt]);
        }
        #pragma unroll
        for (int ng=0; ng<2; ng++){
            uint32_t addr = bHi + (uint32_t)(colBase + ng*16)*KC_STR + bRowOff + kb;
            uint32_t bh[4], bl[4];
            ldsm4(addr, bh);
            ldsm4(addr + (bLo - bHi), bl);
            #pragma unroll
            for (int half=0; half<2; half++){
                int n = ng*2 + half;
                #pragma unroll
                for (int mt=0;mt<2;mt++){
                    mma16816(acc[mt][n], ah[mt], bh[half*2], bh[half*2+1]);
                    mma16816(acc[mt][n], ah[mt], bl[half*2], bl[half*2+1]);
                    mma16816(acc[mt][n], al[mt], bh[half*2], bh[half*2+1]);
                }
            }
        }
    }
}

__global__ void __launch_bounds__(256, 4) kC(const float* __restrict__ M_raw,
                                             const float* __restrict__ bo,
                                             float* __restrict__ outp){
    extern __shared__ __align__(1024) char sm[];
    uint32_t smb = smem_u32(sm);
    int r = blockIdx.y; int s0 = blockIdx.x*SKC; int t = threadIdx.x;
    int wid = t>>5, lane = t&31;

    float* cgp  = (float*)(sm + OFF_CG);
    float* dgbp = (float*)(sm + OFF_DGB);
    float* bop  = (float*)(sm + OFF_BO);
    float2* stp = (float2*)(sm + OFF_STATS);

    #pragma unroll
    for (int i=0;i<8;i++){
        int f = t + i*256; int row = f>>4, c4 = f&15;
        float4 v = *(const float4*)(M_raw + ((size_t)(s0+row)*R + r)*DN + c4*4);
        uint32_t lo0, hi0 = bsplit2(v.x, v.y, lo0);
        uint32_t lo1, hi1 = bsplit2(v.z, v.w, lo1);
        uint32_t off = (uint32_t)row*KC_STR + c4*8;
        *(uint2*)(sm + OFF_AHI + off) = make_uint2(hi0, hi1);
        *(uint2*)(sm + OFF_ALO + off) = make_uint2(lo0, lo1);
    }
    {
        const uint4* s1h = (const uint4*)d_W1h;
        const uint4* s1l = (const uint4*)d_W1l;
        uint4* th = (uint4*)(sm + OFF_WH);
        uint4* tl = (uint4*)(sm + OFF_WL);
        #pragma unroll
        for (int i=0;i<3;i++){
            int f = t + i*256;
            if (f < 576){ th[f]=s1h[f]; tl[f]=s1l[f]; }
        }
    }
    if (t<128) stp[t] = d_stats[(size_t)r*S + s0 + t];
    if (t<64){ cgp[t]=d_cg[t]; dgbp[t]=d_dgb[t]; bop[t]=bo[t]; }
    __syncthreads();

    int rowBase = (wid>>1)*32;
    int colBase = (wid&1)*32;
    float acc[2][4][4];
    #pragma unroll
    for (int mt=0;mt<2;mt++)
        #pragma unroll
        for (int n=0;n<4;n++)
            #pragma unroll
            for (int c=0;c<4;c++) acc[mt][n][c]=0.f;

    gemm_mma(smb+OFF_AHI, smb+OFF_ALO, smb+OFF_WH, smb+OFF_WL, lane, rowBase, colBase, acc);

    // ---- gate transform IN REGISTERS (before sync) ----
    #pragma unroll
    for (int mt=0;mt<2;mt++){
        int row0 = rowBase + mt*16 + (lane>>2);
        int row1 = row0 + 8;
        float2 st0 = stp[row0], st1 = stp[row1];
        float f1a = st0.y, f0a = -st0.y*st0.x;
        float f1b = st1.y, f0b = -st1.y*st1.x;
        #pragma unroll
        for (int n=0;n<4;n++){
            int j = colBase + n*8 + (lane&3)*2;
            float cg0=cgp[j], cg1=cgp[j+1], db0=dgbp[j], db1=dgbp[j+1];
            float z00 = fmaf(f1a, acc[mt][n][0], fmaf(f0a, cg0, db0));
            float z01 = fmaf(f1a, acc[mt][n][1], fmaf(f0a, cg1, db1));
            float z10 = fmaf(f1b, acc[mt][n][2], fmaf(f0b, cg0, db0));
            float z11 = fmaf(f1b, acc[mt][n][3], fmaf(f0b, cg1, db1));
            acc[mt][n][0] = __fdividef(1.f, 1.f + __expf(-z00));
            acc[mt][n][1] = __fdividef(1.f, 1.f + __expf(-z01));
            acc[mt][n][2] = __fdividef(1.f, 1.f + __expf(-z10));
            acc[mt][n][3] = __fdividef(1.f, 1.f + __expf(-z11));
        }
    }
    __syncthreads();   // RACE FIX: all GEMM1 A-reads done before G overwrites A

    #pragma unroll
    for (int mt=0;mt<2;mt++){
        int row0 = rowBase + mt*16 + (lane>>2);
        int row1 = row0 + 8;
        #pragma unroll
        for (int n=0;n<4;n++){
            int j = colBase + n*8 + (lane&3)*2;
            uint32_t lo, hi;
            hi = bsplit2(acc[mt][n][0], acc[mt][n][1], lo);
            uint32_t off0 = (uint32_t)row0*KC_STR + 2*j;
            *(uint32_t*)(sm + OFF_AHI + off0) = hi;
            *(uint32_t*)(sm + OFF_ALO + off0) = lo;
            hi = bsplit2(acc[mt][n][2], acc[mt][n][3], lo);
            uint32_t off1 = (uint32_t)row1*KC_STR + 2*j;
            *(uint32_t*)(sm + OFF_AHI + off1) = hi;
            *(uint32_t*)(sm + OFF_ALO + off1) = lo;
        }
    }
    __syncthreads();

    {
        const uint4* s2h = (const uint4*)(d_W2h + (size_t)r*WPAD);
        const uint4* s2l = (const uint4*)(d_W2l + (size_t)r*WPAD);
        uint4* th = (uint4*)(sm + OFF_WH);
        uint4* tl = (uint4*)(sm + OFF_WL);
        #pragma unroll
        for (int i=0;i<3;i++){
            int f = t + i*256;
            if (f < 576){ th[f]=s2h[f]; tl[f]=s2l[f]; }
        }
    }
    __syncthreads();

    #pragma unroll
    for (int mt=0;mt<2;mt++)
        #pragma unroll
        for (int n=0;n<4;n++)
            #pragma unroll
            for (int c=0;c<4;c++) acc[mt][n][c]=0.f;

    gemm_mma(smb+OFF_AHI, smb+OFF_ALO, smb+OFF_WH, smb+OFF_WL, lane, rowBase, colBase, acc);

    #pragma unroll
    for (int mt=0;mt<2;mt++){
        int row0 = rowBase + mt*16 + (lane>>2);
        int row1 = row0 + 8;
        const float* xb0 = M_raw + ((size_t)(s0+row0)*R + r)*DN;
        const float* xb1 = M_raw + ((size_t)(s0+row1)*R + r)*DN;
        float* ob0 = outp + ((size_t)(s0+row0)*R + r)*DN;
        float* ob1 = outp + ((size_t)(s0+row1)*R + r)*DN;
        #pragma unroll
        for (int n=0;n<4;n++){
            int j = colBase + n*8 + (lane&3)*2;
            float b0v=bop[j], b1v=bop[j+1];
            float2 x0 = *(const float2*)(xb0 + j);
            float2 x1 = *(const float2*)(xb1 + j);
            *(float2*)(ob0 + j) = make_float2(acc[mt][n][0]+b0v+x0.x, acc[mt][n][1]+b1v+x0.y);
            *(float2*)(ob1 + j) = make_float2(acc[mt][n][2]+b0v+x1.x, acc[mt][n][3]+b1v+x1.y);
        }
    }
}

// ---------------- launch ----------------
extern "C" void kernel_launch(void* const* d_in, const int* in_sizes, int n_in,
                              void* d_out, int out_size) {
    const float* M_raw  = (const float*)d_in[0];
    const float* M_mask = (const float*)d_in[1];
    const float* ln_g   = (const float*)d_in[2];
    const float* ln_b   = (const float*)d_in[3];
    const float* Wq     = (const float*)d_in[4];
    const float* Wk     = (const float*)d_in[5];
    const float* Wv     = (const float*)d_in[6];
    const float* Wg     = (const float*)d_in[7];
    const float* bg     = (const float*)d_in[8];
    const float* Wo     = (const float*)d_in[9];
    const float* bo     = (const float*)d_in[10];
    float* outp = (float*)d_out;

    static bool attr_done = false;
    if (!attr_done) {
        cudaFuncSetAttribute(kC, cudaFuncAttributeMaxDynamicSharedMemorySize, SMEM_KC);
        attr_done = true;
    }

    k0<<<1, 256>>>(ln_g, ln_b, Wk, Wv, Wg, bg);
    kA<<<dim3(NST, R), 256>>>(M_raw, M_mask);
    kB<<<R, 256>>>(Wq, ln_g, ln_b, Wo);
    kC<<<dim3(NKC, R), 256, SMEM_KC>>>(M_raw, bo, outp);
}

// round 14
// speedup vs baseline: 1.0599x; 1.0391x over previous
#include <cuda_runtime.h>
#include <cuda_bf16.h>
#include <math.h>
#include <stdint.h>

#define S 2048
#define R 384
#define DN 64
#define STILE 64
#define NST (S/STILE)   // 32 tiles for kA
#define SKC 128         // s-rows per kC block
#define NKC (S/SKC)     // 16
#define WPAD 2304       // uint32 words per padded 64x144B weight tile

// ---------------- scratch (static device memory; no allocations) ----------------
__device__ __align__(16) float  d_kv[R*S*16];        // per (r,s): k[8], v[8]
__device__ __align__(16) float2 d_stats[R*S];        // per (r,s): (mu, rstd)
__device__ __align__(16) float  d_maskT[R*S];        // mask transposed [r][s]
__device__ __align__(16) float  d_qpart[R*NST*64];   // masked-pool partials
__device__ float d_t0part[R*NST];
__device__ float d_cntpart[R*NST];
__device__ __align__(16) float d_obuf[R*64];         // attention output per residue
__device__ float d_cg[64], d_dgb[64], d_ckv[16], d_dkv[16];
// padded-LDSM-layout bf16 weight tiles (hi/lo split)
__device__ __align__(16) uint32_t d_W1h[WPAD], d_W1l[WPAD];
__device__ __align__(16) uint32_t d_W2h[R*WPAD], d_W2l[R*WPAD];
__device__ __align__(16) uint32_t d_Wkvh[576], d_Wkvl[576];  // 16 rows x 144B

// ---------------- helpers ----------------
__device__ __forceinline__ uint32_t smem_u32(const void* p){
    uint32_t a;
    asm("{ .reg .u64 t; cvta.to.shared.u64 t, %1; cvt.u32.u64 %0, t; }" : "=r"(a) : "l"(p));
    return a;
}
__device__ __forceinline__ void ldsm4(uint32_t addr, uint32_t r[4]){
    asm volatile("ldmatrix.sync.aligned.m8n8.x4.shared.b16 {%0,%1,%2,%3}, [%4];"
        : "=r"(r[0]),"=r"(r[1]),"=r"(r[2]),"=r"(r[3]) : "r"(addr));
}
__device__ __forceinline__ void ldsm2(uint32_t addr, uint32_t r[2]){
    asm volatile("ldmatrix.sync.aligned.m8n8.x2.shared.b16 {%0,%1}, [%2];"
        : "=r"(r[0]),"=r"(r[1]) : "r"(addr));
}
__device__ __forceinline__ void mma16816(float c[4], const uint32_t a[4], uint32_t b0, uint32_t b1){
    asm volatile("mma.sync.aligned.m16n8k16.row.col.f32.bf16.bf16.f32 "
        "{%0,%1,%2,%3}, {%4,%5,%6,%7}, {%8,%9}, {%0,%1,%2,%3};"
        : "+f"(c[0]),"+f"(c[1]),"+f"(c[2]),"+f"(c[3])
        : "r"(a[0]),"r"(a[1]),"r"(a[2]),"r"(a[3]), "r"(b0),"r"(b1));
}
__device__ __forceinline__ void bsplit(float x, unsigned short& h, unsigned short& l){
    __nv_bfloat16 hb = __float2bfloat16_rn(x);
    float rrem = x - __bfloat162float(hb);
    __nv_bfloat16 lb = __float2bfloat16_rn(rrem);
    h = __bfloat16_as_ushort(hb); l = __bfloat16_as_ushort(lb);
}
__device__ __forceinline__ uint32_t bsplit2(float x0, float x1, uint32_t& lo){
    unsigned short h0,h1,l0,l1;
    bsplit(x0,h0,l0); bsplit(x1,h1,l1);
    lo = ((uint32_t)l1<<16)|l0;
    return ((uint32_t)h1<<16)|h0;
}

// ---------------- kernel 0: LN-folded weight precompute ----------------
__global__ void k0(const float* __restrict__ ln_g, const float* __restrict__ ln_b,
                   const float* __restrict__ Wk, const float* __restrict__ Wv,
                   const float* __restrict__ Wg, const float* __restrict__ bg){
    int t = threadIdx.x;
    for (int i=0;i<8;i++){
        int f = t + i*256;
        int j = f>>5, kp = f&31;
        float v0 = ln_g[2*kp]  *Wg[(2*kp)*64 + j];
        float v1 = ln_g[2*kp+1]*Wg[(2*kp+1)*64 + j];
        uint32_t lo, hi = bsplit2(v0, v1, lo);
        uint32_t w = (j*144 + 4*kp)>>2;
        d_W1h[w] = hi; d_W1l[w] = lo;
    }
    for (int i=t; i<512; i+=256){
        int c = i>>5, kp = i&31;
        int k0i = 2*kp, k1i = 2*kp+1;
        float w0 = (c<8) ? Wk[k0i*8+c] : Wv[k0i*8+(c-8)];
        float w1 = (c<8) ? Wk[k1i*8+c] : Wv[k1i*8+(c-8)];
        float v0 = ln_g[k0i]*w0, v1 = ln_g[k1i]*w1;
        uint32_t lo, hi = bsplit2(v0, v1, lo);
        uint32_t w = (c*144 + 4*kp)>>2;
        d_Wkvh[w] = hi; d_Wkvl[w] = lo;
    }
    if (t<64){
        float a=0.f, b=0.f;
        for (int k=0;k<64;k++){ a = fmaf(ln_g[k], Wg[k*64+t], a); b = fmaf(ln_b[k], Wg[k*64+t], b); }
        d_cg[t]=a; d_dgb[t]=b+bg[t];
    } else if (t<80){
        int c=t-64; float a=0.f, b=0.f;
        for (int k=0;k<64;k++){
            float wv = (c<8)?Wk[k*8+c]:Wv[k*8+(c-8)];
            a = fmaf(ln_g[k], wv, a); b = fmaf(ln_b[k], wv, b);
        }
        d_ckv[c]=a; d_dkv[c]=b;
    }
}

// ---------------- kernel A: stats + q-pool partials + mma kv GEMM ----------------
__global__ void __launch_bounds__(256) kA(const float* __restrict__ M_raw,
                                          const float* __restrict__ M_mask){
    __shared__ __align__(16) float Xs[64*68];
    __shared__ __align__(16) char Ahi[64*144];
    __shared__ __align__(16) char Alo[64*144];
    __shared__ __align__(16) char Wh[16*144];
    __shared__ __align__(16) char Wl[16*144];
    __shared__ float mus[64], rss[64], msk[64], wrow[64];
    __shared__ float qp[4][64];
    __shared__ float sckv[16], sdkv[16];
    int r = blockIdx.y; int s0 = blockIdx.x*STILE; int t = threadIdx.x;
    int wid = t>>5, lane = t&31;

    if (t<16){ sckv[t]=d_ckv[t]; sdkv[t]=d_dkv[t]; }
    if (t<144){
        ((uint4*)Wh)[t] = ((const uint4*)d_Wkvh)[t];
        ((uint4*)Wl)[t] = ((const uint4*)d_Wkvl)[t];
    }

    #pragma unroll
    for (int i=0;i<4;i++){
        int f = t + i*256; int s = f>>4, c4 = f&15;
        float4 v = *(const float4*)(M_raw + ((size_t)(s0+s)*R + r)*DN + c4*4);
        *(float4*)(Xs + s*68 + c4*4) = v;
        uint32_t lo0, hi0 = bsplit2(v.x, v.y, lo0);
        uint32_t lo1, hi1 = bsplit2(v.z, v.w, lo1);
        uint32_t off = (uint32_t)s*144 + c4*8;
        *(uint2*)(Ahi + off) = make_uint2(hi0, hi1);
        *(uint2*)(Alo + off) = make_uint2(lo0, lo1);
    }
    __syncthreads();

    {
        int row = t>>2, p = t&3;
        float sm1=0.f, sq=0.f;
        #pragma unroll
        for (int i=0;i<4;i++){
            float4 v = *(float4*)(Xs + row*68 + p*16 + i*4);
            sm1 += (v.x+v.y)+(v.z+v.w);
            sq = fmaf(v.x,v.x,sq); sq=fmaf(v.y,v.y,sq); sq=fmaf(v.z,v.z,sq); sq=fmaf(v.w,v.w,sq);
        }
        sm1 += __shfl_xor_sync(0xffffffffu, sm1, 1); sq += __shfl_xor_sync(0xffffffffu, sq, 1);
        sm1 += __shfl_xor_sync(0xffffffffu, sm1, 2); sq += __shfl_xor_sync(0xffffffffu, sq, 2);
        if (p==0){
            float mu = sm1*(1.f/64.f);
            float var = fmaf(-mu, mu, sq*(1.f/64.f));
            float rstd = rsqrtf(var + 1e-5f);
            float m = M_mask[(size_t)(s0+row)*R + r];
            mus[row]=mu; rss[row]=rstd; msk[row]=m; wrow[row]=m*rstd;
            d_stats[(size_t)r*S + s0 + row] = make_float2(mu, rstd);
            d_maskT[(size_t)r*S + s0 + row] = m;
        }
    }
    __syncthreads();

    {
        int d = t&63, i4 = t>>6;
        float a = 0.f;
        #pragma unroll 4
        for (int rw = i4*16; rw < i4*16+16; rw++)
            a = fmaf(wrow[rw], Xs[rw*68+d], a);
        qp[i4][d] = a;
    }
    __syncthreads();
    if (t<64){
        d_qpart[((size_t)r*NST + blockIdx.x)*64 + t] = qp[0][t]+qp[1][t]+qp[2][t]+qp[3][t];
    } else if (t==64){
        float a=0.f; for (int rw=0;rw<64;rw++) a = fmaf(wrow[rw], mus[rw], a);
        d_t0part[r*NST + blockIdx.x] = a;
    } else if (t==65){
        float a=0.f; for (int rw=0;rw<64;rw++) a += msk[rw];
        d_cntpart[r*NST + blockIdx.x] = a;
    }

    { // kv GEMM via mma.sync
        int rowBase = (wid>>1)*16, colBase = (wid&1)*8;
        uint32_t aBaseH = smem_u32(Ahi), aBaseL = smem_u32(Alo);
        uint32_t bBaseH = smem_u32(Wh),  bBaseL = smem_u32(Wl);
        uint32_t aOff = (uint32_t)(rowBase + (lane&7) + ((lane>>3)&1)*8)*144 + ((lane>>4)&1)*16;
        uint32_t bOff = (uint32_t)(colBase + (lane&7))*144 + ((lane>>3)&1)*16;
        float c[4] = {0.f,0.f,0.f,0.f};
        #pragma unroll
        for (int k=0;k<4;k++){
            uint32_t kb = k*32;
            uint32_t ah[4], al[4], bh[2], bl[2];
            ldsm4(aBaseH + aOff + kb, ah);
            ldsm4(aBaseL + aOff + kb, al);
            ldsm2(bBaseH + bOff + kb, bh);
            ldsm2(bBaseL + bOff + kb, bl);
            mma16816(c, ah, bh[0], bh[1]);
            mma16816(c, ah, bl[0], bl[1]);
            mma16816(c, al, bh[0], bh[1]);
        }
        int sl0 = rowBase + (lane>>2), sl1 = sl0 + 8;
        int cc = colBase + (lane&3)*2;
        float f1a = rss[sl0], f0a = -rss[sl0]*mus[sl0];
        float f1b = rss[sl1], f0b = -rss[sl1]*mus[sl1];
        float2 o0, o1;
        o0.x = fmaf(f1a, c[0], fmaf(f0a, sckv[cc],   sdkv[cc]));
        o0.y = fmaf(f1a, c[1], fmaf(f0a, sckv[cc+1], sdkv[cc+1]));
        o1.x = fmaf(f1b, c[2], fmaf(f0b, sckv[cc],   sdkv[cc]));
        o1.y = fmaf(f1b, c[3], fmaf(f0b, sckv[cc+1], sdkv[cc+1]));
        *(float2*)(d_kv + ((size_t)r*S + s0 + sl0)*16 + cc) = o0;
        *(float2*)(d_kv + ((size_t)r*S + s0 + sl1)*16 + cc) = o1;
    }
}

// ---------------- kernel B: one-pass online-softmax attention -> o[r][64]; builds W2 ----------------
__global__ void __launch_bounds__(256) kB(const float* __restrict__ Wq,
                                          const float* __restrict__ ln_g,
                                          const float* __restrict__ ln_b,
                                          const float* __restrict__ Wo){
    __shared__ float qa[64], qs[64];
    __shared__ float t0c[2];
    __shared__ float wred[8][80];
    __shared__ float mx[8];
    __shared__ float tot[72];
    __shared__ float oos[64];
    int r = blockIdx.x, t = threadIdx.x;
    int lane = t&31, w = t>>5;

    if (t<64){
        float a=0.f;
        #pragma unroll 4
        for (int ch=0; ch<NST; ch++) a += d_qpart[((size_t)r*NST+ch)*64 + t];
        qa[t] = a;
    } else if (t==64){
        float a=0.f,c=0.f;
        for (int ch=0; ch<NST; ch++){ a += d_t0part[r*NST+ch]; c += d_cntpart[r*NST+ch]; }
        t0c[0]=a; t0c[1]=c;
    }
    __syncthreads();
    if (t<64){
        float T0=t0c[0], cnt=t0c[1];
        qa[t] = (ln_g[t]*(qa[t]-T0) + ln_b[t]*cnt) * __fdividef(1.f, cnt + 1e-10f);
    }
    __syncthreads();
    if (t<64){
        float a=0.f;
        #pragma unroll
        for (int d=0; d<64; d++) a = fmaf(qa[d], Wq[d*64+t], a);
        qs[t] = a * 0.35355339059327373f;
    }
    __syncthreads();

    const float* kvr = d_kv + (size_t)r*S*16;
    const float* mr  = d_maskT + (size_t)r*S;

    float lmax[8], esum[8], acc[64];
    #pragma unroll
    for (int h=0;h<8;h++){ lmax[h] = -3.0e38f; esum[h]=0.f; }
    #pragma unroll
    for (int i=0;i<64;i++) acc[i]=0.f;

    for (int it=0; it<8; it++){
        int s = t + it*256;
        float4 kk0 = *(const float4*)(kvr + s*16);
        float4 kk1 = *(const float4*)(kvr + s*16 + 4);
        float4 v0  = *(const float4*)(kvr + s*16 + 8);
        float4 v1  = *(const float4*)(kvr + s*16 + 12);
        float bias = 1e9f*(mr[s]-1.f);
        #pragma unroll
        for (int h=0;h<8;h++){
            const float* q = qs + h*8;
            float l = bias;
            l=fmaf(q[0],kk0.x,l); l=fmaf(q[1],kk0.y,l); l=fmaf(q[2],kk0.z,l); l=fmaf(q[3],kk0.w,l);
            l=fmaf(q[4],kk1.x,l); l=fmaf(q[5],kk1.y,l); l=fmaf(q[6],kk1.z,l); l=fmaf(q[7],kk1.w,l);
            if (l > lmax[h]){
                float sc = __expf(lmax[h] - l);
                esum[h] *= sc;
                #pragma unroll
                for (int c=0;c<8;c++) acc[h*8+c] *= sc;
                lmax[h] = l;
            }
            float e = __expf(l - lmax[h]);
            esum[h] += e;
            acc[h*8+0]=fmaf(e,v0.x,acc[h*8+0]); acc[h*8+1]=fmaf(e,v0.y,acc[h*8+1]);
            acc[h*8+2]=fmaf(e,v0.z,acc[h*8+2]); acc[h*8+3]=fmaf(e,v0.w,acc[h*8+3]);
            acc[h*8+4]=fmaf(e,v1.x,acc[h*8+4]); acc[h*8+5]=fmaf(e,v1.y,acc[h*8+5]);
            acc[h*8+6]=fmaf(e,v1.z,acc[h*8+6]); acc[h*8+7]=fmaf(e,v1.w,acc[h*8+7]);
        }
    }

    #pragma unroll
    for (int h=0;h<8;h++){
        float v = lmax[h];
        v = fmaxf(v, __shfl_xor_sync(0xffffffffu,v,16));
        v = fmaxf(v, __shfl_xor_sync(0xffffffffu,v,8));
        v = fmaxf(v, __shfl_xor_sync(0xffffffffu,v,4));
        v = fmaxf(v, __shfl_xor_sync(0xffffffffu,v,2));
        v = fmaxf(v, __shfl_xor_sync(0xffffffffu,v,1));
        if (lane==0) wred[w][h] = v;
    }
    __syncthreads();
    if (t<8){
        float v = wred[0][t];
        #pragma unroll
        for (int i=1;i<8;i++) v = fmaxf(v, wred[i][t]);
        mx[t]=v;
    }
    __syncthreads();

    #pragma unroll
    for (int h=0;h<8;h++){
        float f = __expf(lmax[h] - mx[h]);
        esum[h] *= f;
        #pragma unroll
        for (int c=0;c<8;c++) acc[h*8+c] *= f;
    }

    #pragma unroll
    for (int i=0;i<64;i++){
        float v = acc[i];
        v += __shfl_xor_sync(0xffffffffu,v,16); v += __shfl_xor_sync(0xffffffffu,v,8);
        v += __shfl_xor_sync(0xffffffffu,v,4);  v += __shfl_xor_sync(0xffffffffu,v,2);
        v += __shfl_xor_sync(0xffffffffu,v,1);
        acc[i]=v;
    }
    #pragma unroll
    for (int h=0;h<8;h++){
        float v = esum[h];
        v += __shfl_xor_sync(0xffffffffu,v,16); v += __shfl_xor_sync(0xffffffffu,v,8);
        v += __shfl_xor_sync(0xffffffffu,v,4);  v += __shfl_xor_sync(0xffffffffu,v,2);
        v += __shfl_xor_sync(0xffffffffu,v,1);
        esum[h]=v;
    }
    __syncthreads();
    if (lane==0){
        #pragma unroll
        for (int i=0;i<64;i++) wred[w][i]=acc[i];
        #pragma unroll
        for (int h=0;h<8;h++) wred[w][64+h]=esum[h];
    }
    __syncthreads();
    if (t<72){
        float v=0.f;
        #pragma unroll
        for (int i=0;i<8;i++) v += wred[i][t];
        tot[t]=v;
    }
    __syncthreads();
    if (t<64){
        float o = __fdividef(tot[t], tot[64+(t>>3)]);
        d_obuf[r*64+t] = o;
        oos[t] = o;
    }
    __syncthreads();

    uint32_t* W2h = d_W2h + (size_t)r*WPAD;
    uint32_t* W2l = d_W2l + (size_t)r*WPAD;
    #pragma unroll
    for (int i=0;i<8;i++){
        int f = t + i*256;
        int d = f>>5, jp = f&31;
        float v0 = Wo[(2*jp)*64 + d]  *oos[2*jp];
        float v1 = Wo[(2*jp+1)*64 + d]*oos[2*jp+1];
        uint32_t lo, hi = bsplit2(v0, v1, lo);
        uint32_t w2 = (d*144 + 4*jp)>>2;
        W2h[w2] = hi; W2l[w2] = lo;
    }
}

// ---------------- kernel C: mma.sync bf16-split gate/output GEMMs ----------------
// Epilogue staged through smem for coalesced gmem I/O.
#define KC_STR    144
#define OFF_AHI   0
#define OFF_ALO   18432
#define OFF_WH    36864
#define OFF_WL    46080
#define OFF_STATS 55296
#define OFF_CG    56320
#define OFF_DGB   56576
#define OFF_BO    56832
#define SMEM_KC   57088

__device__ __forceinline__ void gemm_mma(uint32_t aHi, uint32_t aLo,
                                         uint32_t bHi, uint32_t bLo,
                                         int lane, int rowBase, int colBase,
                                         float acc[2][4][4]){
    uint32_t aRowOff = (uint32_t)((lane&7) + ((lane>>3)&1)*8) * KC_STR + ((lane>>4)&1)*16;
    uint32_t bRowOff = (uint32_t)((lane&7) + ((lane>>4)&1)*8) * KC_STR + ((lane>>3)&1)*16;
    #pragma unroll
    for (int k=0;k<4;k++){
        uint32_t kb = k*32;
        uint32_t ah[2][4], al[2][4];
        #pragma unroll
        for (int mt=0;mt<2;mt++){
            uint32_t addr = aHi + (uint32_t)(rowBase + mt*16)*KC_STR + aRowOff + kb;
            ldsm4(addr, ah[mt]);
            ldsm4(addr + (aLo - aHi), al[mt]);
        }
        #pragma unroll
        for (int ng=0; ng<2; ng++){
            uint32_t addr = bHi + (uint32_t)(colBase + ng*16)*KC_STR + bRowOff + kb;
            uint32_t bh[4], bl[4];
            ldsm4(addr, bh);
            ldsm4(addr + (bLo - bHi), bl);
            #pragma unroll
            for (int half=0; half<2; half++){
                int n = ng*2 + half;
                #pragma unroll
                for (int mt=0;mt<2;mt++){
                    mma16816(acc[mt][n], ah[mt], bh[half*2], bh[half*2+1]);
                    mma16816(acc[mt][n], ah[mt], bl[half*2], bl[half*2+1]);
                    mma16816(acc[mt][n], al[mt], bh[half*2], bh[half*2+1]);
                }
            }
        }
    }
}

__global__ void __launch_bounds__(256, 4) kC(const float* __restrict__ M_raw,
                                             const float* __restrict__ bo,
                                             float* __restrict__ outp){
    extern __shared__ __align__(1024) char sm[];
    uint32_t smb = smem_u32(sm);
    int r = blockIdx.y; int s0 = blockIdx.x*SKC; int t = threadIdx.x;
    int wid = t>>5, lane = t&31;

    float* cgp  = (float*)(sm + OFF_CG);
    float* dgbp = (float*)(sm + OFF_DGB);
    float* bop  = (float*)(sm + OFF_BO);
    float2* stp = (float2*)(sm + OFF_STATS);

    #pragma unroll
    for (int i=0;i<8;i++){
        int f = t + i*256; int row = f>>4, c4 = f&15;
        float4 v = *(const float4*)(M_raw + ((size_t)(s0+row)*R + r)*DN + c4*4);
        uint32_t lo0, hi0 = bsplit2(v.x, v.y, lo0);
        uint32_t lo1, hi1 = bsplit2(v.z, v.w, lo1);
        uint32_t off = (uint32_t)row*KC_STR + c4*8;
        *(uint2*)(sm + OFF_AHI + off) = make_uint2(hi0, hi1);
        *(uint2*)(sm + OFF_ALO + off) = make_uint2(lo0, lo1);
    }
    {
        const uint4* s1h = (const uint4*)d_W1h;
        const uint4* s1l = (const uint4*)d_W1l;
        uint4* th = (uint4*)(sm + OFF_WH);
        uint4* tl = (uint4*)(sm + OFF_WL);
        #pragma unroll
        for (int i=0;i<3;i++){
            int f = t + i*256;
            if (f < 576){ th[f]=s1h[f]; tl[f]=s1l[f]; }
        }
    }
    if (t<128) stp[t] = d_stats[(size_t)r*S + s0 + t];
    if (t<64){ cgp[t]=d_cg[t]; dgbp[t]=d_dgb[t]; bop[t]=bo[t]; }
    __syncthreads();

    int rowBase = (wid>>1)*32;
    int colBase = (wid&1)*32;
    float acc[2][4][4];
    #pragma unroll
    for (int mt=0;mt<2;mt++)
        #pragma unroll
        for (int n=0;n<4;n++)
            #pragma unroll
            for (int c=0;c<4;c++) acc[mt][n][c]=0.f;

    gemm_mma(smb+OFF_AHI, smb+OFF_ALO, smb+OFF_WH, smb+OFF_WL, lane, rowBase, colBase, acc);

    // ---- gate transform IN REGISTERS (before sync) ----
    #pragma unroll
    for (int mt=0;mt<2;mt++){
        int row0 = rowBase + mt*16 + (lane>>2);
        int row1 = row0 + 8;
        float2 st0 = stp[row0], st1 = stp[row1];
        float f1a = st0.y, f0a = -st0.y*st0.x;
        float f1b = st1.y, f0b = -st1.y*st1.x;
        #pragma unroll
        for (int n=0;n<4;n++){
            int j = colBase + n*8 + (lane&3)*2;
            float cg0=cgp[j], cg1=cgp[j+1], db0=dgbp[j], db1=dgbp[j+1];
            float z00 = fmaf(f1a, acc[mt][n][0], fmaf(f0a, cg0, db0));
            float z01 = fmaf(f1a, acc[mt][n][1], fmaf(f0a, cg1, db1));
            float z10 = fmaf(f1b, acc[mt][n][2], fmaf(f0b, cg0, db0));
            float z11 = fmaf(f1b, acc[mt][n][3], fmaf(f0b, cg1, db1));
            acc[mt][n][0] = __fdividef(1.f, 1.f + __expf(-z00));
            acc[mt][n][1] = __fdividef(1.f, 1.f + __expf(-z01));
            acc[mt][n][2] = __fdividef(1.f, 1.f + __expf(-z10));
            acc[mt][n][3] = __fdividef(1.f, 1.f + __expf(-z11));
        }
    }
    __syncthreads();   // RACE FIX: all GEMM1 A-reads done before G overwrites A

    #pragma unroll
    for (int mt=0;mt<2;mt++){
        int row0 = rowBase + mt*16 + (lane>>2);
        int row1 = row0 + 8;
        #pragma unroll
        for (int n=0;n<4;n++){
            int j = colBase + n*8 + (lane&3)*2;
            uint32_t lo, hi;
            hi = bsplit2(acc[mt][n][0], acc[mt][n][1], lo);
            uint32_t off0 = (uint32_t)row0*KC_STR + 2*j;
            *(uint32_t*)(sm + OFF_AHI + off0) = hi;
            *(uint32_t*)(sm + OFF_ALO + off0) = lo;
            hi = bsplit2(acc[mt][n][2], acc[mt][n][3], lo);
            uint32_t off1 = (uint32_t)row1*KC_STR + 2*j;
            *(uint32_t*)(sm + OFF_AHI + off1) = hi;
            *(uint32_t*)(sm + OFF_ALO + off1) = lo;
        }
    }
    __syncthreads();

    {
        const uint4* s2h = (const uint4*)(d_W2h + (size_t)r*WPAD);
        const uint4* s2l = (const uint4*)(d_W2l + (size_t)r*WPAD);
        uint4* th = (uint4*)(sm + OFF_WH);
        uint4* tl = (uint4*)(sm + OFF_WL);
        #pragma unroll
        for (int i=0;i<3;i++){
            int f = t + i*256;
            if (f < 576){ th[f]=s2h[f]; tl[f]=s2l[f]; }
        }
    }
    __syncthreads();

    #pragma unroll
    for (int mt=0;mt<2;mt++)
        #pragma unroll
        for (int n=0;n<4;n++)
            #pragma unroll
            for (int c=0;c<4;c++) acc[mt][n][c]=0.f;

    gemm_mma(smb+OFF_AHI, smb+OFF_ALO, smb+OFF_WH, smb+OFF_WL, lane, rowBase, colBase, acc);

    // ---- epilogue: stage acc through smem, then coalesced residual+store ----
    __syncthreads();   // all GEMM2 reads of A/G tiles done; A region now reusable
    {
        float* res = (float*)(sm + OFF_AHI);   // 128 x 68 floats = 34816 B (< 36864)
        #pragma unroll
        for (int mt=0;mt<2;mt++){
            int row0 = rowBase + mt*16 + (lane>>2);
            int row1 = row0 + 8;
            #pragma unroll
            for (int n=0;n<4;n++){
                int j = colBase + n*8 + (lane&3)*2;
                *(float2*)(res + row0*68 + j) = make_float2(acc[mt][n][0], acc[mt][n][1]);
                *(float2*)(res + row1*68 + j) = make_float2(acc[mt][n][2], acc[mt][n][3]);
            }
        }
    }
    __syncthreads();
    {
        const float* res = (const float*)(sm + OFF_AHI);
        #pragma unroll
        for (int i=0;i<8;i++){
            int f = t + i*256; int row = f>>4, c4 = f&15;
            size_t gidx = ((size_t)(s0+row)*R + r)*DN + c4*4;
            float4 x = *(const float4*)(M_raw + gidx);
            float4 v = *(const float4*)(res + row*68 + c4*4);
            float4 b = *(const float4*)(bop + c4*4);
            float4 o;
            o.x = v.x + b.x + x.x;
            o.y = v.y + b.y + x.y;
            o.z = v.z + b.z + x.z;
            o.w = v.w + b.w + x.w;
            *(float4*)(outp + gidx) = o;
        }
    }
}

// ---------------- launch ----------------
extern "C" void kernel_launch(void* const* d_in, const int* in_sizes, int n_in,
                              void* d_out, int out_size) {
    const float* M_raw  = (const float*)d_in[0];
    const float* M_mask = (const float*)d_in[1];
    const float* ln_g   = (const float*)d_in[2];
    const float* ln_b   = (const float*)d_in[3];
    const float* Wq     = (const float*)d_in[4];
    const float* Wk     = (const float*)d_in[5];
    const float* Wv     = (const float*)d_in[6];
    const float* Wg     = (const float*)d_in[7];
    const float* bg     = (const float*)d_in[8];
    const float* Wo     = (const float*)d_in[9];
    const float* bo     = (const float*)d_in[10];
    float* outp = (float*)d_out;

    static bool attr_done = false;
    if (!attr_done) {
        cudaFuncSetAttribute(kC, cudaFuncAttributeMaxDynamicSharedMemorySize, SMEM_KC);
        attr_done = true;
    }

    k0<<<1, 256>>>(ln_g, ln_b, Wk, Wv, Wg, bg);
    kA<<<dim3(NST, R), 256>>>(M_raw, M_mask);
    kB<<<R, 256>>>(Wq, ln_g, ln_b, Wo);
    kC<<<dim3(NKC, R), 256, SMEM_KC>>>(M_raw, bo, outp);
}